// round 16
// baseline (speedup 1.0000x reference)
#include <cuda_runtime.h>
#include <cuda_bf16.h>
#include <cuda_fp16.h>
#include <math.h>
#include <stdint.h>

#define Bsz   4096
#define THW   1152
#define LN_EPS 1e-5f

#define OFF_H ((size_t)Bsz * 1024)
#define OFF_C (OFF_H + (size_t)Bsz * THW)
#define OUT_FULL_SIZE (OFF_C + (size_t)Bsz * THW)

// ---------------- scratch ----------------
__device__ __half g_xh_hi[(size_t)Bsz * 2048];
__device__ __half g_xh_lo[(size_t)Bsz * 2048];
__device__ __half g_wm_hi[(size_t)2 * 4096 * 1024];
__device__ __half g_awih_hi[(size_t)512 * 2048];
__device__ __half g_ah_hi[(size_t)Bsz * 128];
__device__ __half g_ah_lo[(size_t)Bsz * 128];
__device__ __half g_awhh_hi[(size_t)512 * 128];
__device__ __nv_bfloat16 g_zwzbHi[(size_t)Bsz * 256];
__device__ __nv_bfloat16 g_zwzbLo[(size_t)Bsz * 256];
__device__ __nv_bfloat16 g_aWHi[131072];
__device__ __nv_bfloat16 g_aWLo[131072];
__device__ __nv_bfloat16 g_bWHi[131072];
__device__ __nv_bfloat16 g_bWLo[131072];
__device__ float g_nwT[128 * 256];
__device__ float g_igpre[(size_t)Bsz * 512];
__device__ float g_hgpre[(size_t)Bsz * 512];
__device__ float g_gates[(size_t)2 * Bsz * 4096];

// ---------------- PTX helpers ----------------
__device__ __forceinline__ uint32_t smem_u32(const void* p) {
    uint32_t a;
    asm("{ .reg .u64 t; cvta.to.shared.u64 t, %1; cvt.u32.u64 %0, t; }" : "=r"(a) : "l"(p));
    return a;
}
__device__ __forceinline__ void cp_async16(uint32_t smaddr, const void* gaddr) {
    asm volatile("cp.async.cg.shared.global [%0], [%1], 16;" :: "r"(smaddr), "l"(gaddr) : "memory");
}
#define CP_COMMIT() asm volatile("cp.async.commit_group;" ::: "memory")
#define CP_WAIT(n)  asm volatile("cp.async.wait_group %0;" :: "n"(n) : "memory")

__device__ __forceinline__ void ldmat4(uint32_t* r, uint32_t addr) {
    asm volatile("ldmatrix.sync.aligned.m8n8.x4.shared.b16 {%0,%1,%2,%3}, [%4];"
        : "=r"(r[0]), "=r"(r[1]), "=r"(r[2]), "=r"(r[3]) : "r"(addr));
}
// bf16 mma (epilogue tables)
__device__ __forceinline__ void mma16816(float* c, const uint32_t* a, const uint32_t* b) {
    asm volatile("mma.sync.aligned.m16n8k16.row.col.f32.bf16.bf16.f32 "
        "{%0,%1,%2,%3}, {%4,%5,%6,%7}, {%8,%9}, {%0,%1,%2,%3};"
        : "+f"(c[0]), "+f"(c[1]), "+f"(c[2]), "+f"(c[3])
        : "r"(a[0]), "r"(a[1]), "r"(a[2]), "r"(a[3]), "r"(b[0]), "r"(b[1]));
}
// fp16 mma (mainloop)
__device__ __forceinline__ void mma16816h(float* c, const uint32_t* a, const uint32_t* b) {
    asm volatile("mma.sync.aligned.m16n8k16.row.col.f32.f16.f16.f32 "
        "{%0,%1,%2,%3}, {%4,%5,%6,%7}, {%8,%9}, {%0,%1,%2,%3};"
        : "+f"(c[0]), "+f"(c[1]), "+f"(c[2]), "+f"(c[3])
        : "r"(a[0]), "r"(a[1]), "r"(a[2]), "r"(a[3]), "r"(b[0]), "r"(b[1]));
}

// ---------------- conversions ----------------
__device__ __forceinline__ void splitA16(const float* src, int srcLd,
                                         __half* hi, __half* lo,
                                         int dstLd, int w8, int idx)
{
    const int r = idx / w8, c = (idx - r * w8) * 8;
    const float* s = src + (size_t)r * srcLd + c;
    float4 v0 = *(const float4*)s;
    float4 v1 = *(const float4*)(s + 4);
    float f[8] = { v0.x, v0.y, v0.z, v0.w, v1.x, v1.y, v1.z, v1.w };
    __half h[8], l[8];
    #pragma unroll
    for (int i = 0; i < 8; ++i) {
        h[i] = __float2half_rn(f[i]);
        l[i] = __float2half_rn(f[i] - __half2float(h[i]));
    }
    *(uint4*)(hi + (size_t)r * dstLd + c) = *(uint4*)h;
    *(uint4*)(lo + (size_t)r * dstLd + c) = *(uint4*)l;
}
__device__ __forceinline__ void cvtB16(const float* src, int srcLd,
                                       __half* hi, int dstLd, int w8, int idx)
{
    const int r = idx / w8, c = (idx - r * w8) * 8;
    const float* s = src + (size_t)r * srcLd + c;
    float4 v0 = *(const float4*)s;
    float4 v1 = *(const float4*)(s + 4);
    float f[8] = { v0.x, v0.y, v0.z, v0.w, v1.x, v1.y, v1.z, v1.w };
    __half h[8];
    #pragma unroll
    for (int i = 0; i < 8; ++i) h[i] = __float2half_rn(f[i]);
    *(uint4*)(hi + (size_t)r * dstLd + c) = *(uint4*)h;
}
__device__ __forceinline__ void splitBF(const float* src, int srcLd,
                                        __nv_bfloat16* hi, __nv_bfloat16* lo,
                                        int dstLd, int w8, int idx)
{
    const int r = idx / w8, c = (idx - r * w8) * 8;
    const float* s = src + (size_t)r * srcLd + c;
    float4 v0 = *(const float4*)s;
    float4 v1 = *(const float4*)(s + 4);
    float f[8] = { v0.x, v0.y, v0.z, v0.w, v1.x, v1.y, v1.z, v1.w };
    __nv_bfloat16 h[8], l[8];
    #pragma unroll
    for (int i = 0; i < 8; ++i) {
        h[i] = __float2bfloat16(f[i]);
        l[i] = __float2bfloat16(f[i] - __bfloat162float(h[i]));
    }
    *(uint4*)(hi + (size_t)r * dstLd + c) = *(uint4*)h;
    *(uint4*)(lo + (size_t)r * dstLd + c) = *(uint4*)l;
}

__global__ __launch_bounds__(256)
void split_all(const float* __restrict__ w_ih, const float* __restrict__ w_hh,
               const float* __restrict__ x, const float* __restrict__ total_h,
               const float* __restrict__ a_w_ih, const float* __restrict__ a_w_hh,
               const float* __restrict__ norm_alpha_w, const float* __restrict__ bias_beta_w,
               const float* __restrict__ norm_zw_w, const float* __restrict__ bias_zb_w,
               __half* __restrict__ wm_hi,
               __half* __restrict__ xh_hi, __half* __restrict__ xh_lo,
               __half* __restrict__ ah_hi, __half* __restrict__ ah_lo,
               __half* __restrict__ awih_hi, __half* __restrict__ awhh_hi,
               __nv_bfloat16* __restrict__ aWHi, __nv_bfloat16* __restrict__ aWLo,
               __nv_bfloat16* __restrict__ bWHi, __nv_bfloat16* __restrict__ bWLo,
               float* __restrict__ nwT)
{
    const int blk = blockIdx.x;
    const int t = threadIdx.x;
    if (blk < 2048)       cvtB16(w_ih, 1024, wm_hi, 1024, 128, blk * 256 + t);
    else if (blk < 4096)  cvtB16(w_hh, 1024, wm_hi + (size_t)4096 * 1024, 1024, 128, (blk - 2048) * 256 + t);
    else if (blk < 6144)  splitA16(x, 1024, xh_hi, xh_lo, 2048, 128, (blk - 4096) * 256 + t);
    else if (blk < 8192)  splitA16(total_h, THW, xh_hi + 1024, xh_lo + 1024, 2048, 128, (blk - 6144) * 256 + t);
    else if (blk < 8448)  splitA16(total_h + 1024, THW, ah_hi, ah_lo, 128, 16, (blk - 8192) * 256 + t);
    else if (blk < 8960)  cvtB16(a_w_ih, 2048, awih_hi, 2048, 256, (blk - 8448) * 256 + t);
    else if (blk < 8992)  cvtB16(a_w_hh, 128, awhh_hi, 128, 16, (blk - 8960) * 256 + t);
    else if (blk < 9056)  splitBF(norm_alpha_w, 131072, aWHi, aWLo, 131072, 16384, (blk - 8992) * 256 + t);
    else if (blk < 9120)  splitBF(bias_beta_w, 131072, bWHi, bWLo, 131072, 16384, (blk - 9056) * 256 + t);
    else {
        int idx = (blk - 9120) * 256 + t;
        int a = idx >> 8, j = idx & 255;
        nwT[a * 256 + j] = (j < 128) ? norm_zw_w[j * 128 + a] : bias_zb_w[(j - 128) * 128 + a];
    }
}

// ================= MAIN GEMM fp16x2: 512 thr, tile 128x256, Kc=64, 3-stage single-sync
// Stage = 64KB: [Ahi 16K][Alo 16K][Bhi 32K].
#define STG_MAIN 65536
#define SMEM_MAIN (3 * STG_MAIN)

__global__ __launch_bounds__(512, 1)
void gemm_main(const __half* __restrict__ Ahi_, const __half* __restrict__ Alo_,
               int lda, int aZoff,
               const __half* __restrict__ Bhi_, long bZ,
               float* __restrict__ C_, int ldc, long cZ, int K,
               const __nv_bfloat16* __restrict__ zwzbHiG, const __nv_bfloat16* __restrict__ zwzbLoG,
               const __nv_bfloat16* __restrict__ aWHiG, const __nv_bfloat16* __restrict__ aWLoG,
               const __nv_bfloat16* __restrict__ bWHiG, const __nv_bfloat16* __restrict__ bWLoG,
               const float* __restrict__ bias0, const float* __restrict__ bias1)
{
    extern __shared__ char smem[];
    const uint32_t sb = smem_u32(smem);

    const int tid  = threadIdx.x;
    const int lane = tid & 31;
    const int wid  = tid >> 5;
    const int wm   = wid >> 2;          // 0..3 -> 32 M rows
    const int wn   = wid & 3;           // 0..3 -> 64 N cols
    const int m0 = blockIdx.y * 128;
    const int n0 = blockIdx.x * 256;
    const int z  = blockIdx.z;

    const __half* Ahi = Ahi_ + (size_t)z * aZoff;
    const __half* Alo = Alo_ + (size_t)z * aZoff;
    const __half* Bhi = Bhi_ + (size_t)z * bZ;
    float* C = C_ + (size_t)z * cZ;

    float acc[2][8][4];
    #pragma unroll
    for (int i = 0; i < 2; i++)
        #pragma unroll
        for (int j = 0; j < 8; j++)
            #pragma unroll
            for (int q = 0; q < 4; q++) acc[i][j][q] = 0.f;

    const int nCh = K >> 6;
    const int ldRow = tid >> 3;
    const int ldSeg = tid & 7;

    auto load_stage = [&](int chunk, int buf) {
        const uint32_t sbase = sb + buf * STG_MAIN;
        const int kcol = chunk * 64;
        #pragma unroll
        for (int it = 0; it < 2; ++it) {
            const int row = ldRow + it * 64;
            const uint32_t so = (row << 7) + ((ldSeg ^ (row & 7)) << 4);
            const size_t ga = (size_t)(m0 + row) * lda + kcol + ldSeg * 8;
            cp_async16(sbase + so,         Ahi + ga);
            cp_async16(sbase + 16384 + so, Alo + ga);
        }
        #pragma unroll
        for (int it = 0; it < 4; ++it) {
            const int row = ldRow + it * 64;
            const uint32_t so = (row << 7) + ((ldSeg ^ (row & 7)) << 4);
            const size_t gb = (size_t)(n0 + row) * K + kcol + ldSeg * 8;
            cp_async16(sbase + 32768 + so, Bhi + gb);
        }
    };

    load_stage(0, 0); CP_COMMIT();
    load_stage(1, 1); CP_COMMIT();

    for (int c = 0; c < nCh; ++c) {
        CP_WAIT(1);
        __syncthreads();
        if (c + 2 < nCh) load_stage(c + 2, (c + 2) % 3);
        CP_COMMIT();

        const uint32_t aHiB = sb + (c % 3) * STG_MAIN;
        const uint32_t aLoB = aHiB + 16384;
        const uint32_t bHiB = aHiB + 32768;

        #pragma unroll
        for (int ks = 0; ks < 4; ++ks) {
            uint32_t ahi[2][4], alo[2][4];
            const int rA = wm * 32 + (lane & 15);
            #pragma unroll
            for (int mi = 0; mi < 2; ++mi) {
                const int row = rA + mi * 16;
                const uint32_t ad = (uint32_t)(row << 7) + (uint32_t)((((ks * 2) + (lane >> 4)) ^ (row & 7)) << 4);
                ldmat4(ahi[mi], aHiB + ad);
                ldmat4(alo[mi], aLoB + ad);
            }
            #pragma unroll
            for (int h = 0; h < 2; ++h) {
                uint32_t bhi[4][2];
                #pragma unroll
                for (int p = 0; p < 2; ++p) {
                    const int P = h * 2 + p;
                    const int mi2 = lane >> 3;
                    const int row = wn * 64 + (P * 2 + (mi2 >> 1)) * 8 + (lane & 7);
                    const uint32_t ad = (uint32_t)(row << 7) + (uint32_t)((((ks * 2) + (mi2 & 1)) ^ (row & 7)) << 4);
                    ldmat4(&bhi[p * 2][0], bHiB + ad);
                }
                #pragma unroll
                for (int mi = 0; mi < 2; ++mi)
                    #pragma unroll
                    for (int nj = 0; nj < 4; ++nj) {
                        mma16816h(acc[mi][h * 4 + nj], ahi[mi], bhi[nj]);
                        mma16816h(acc[mi][h * 4 + nj], alo[mi], bhi[nj]);
                    }
            }
        }
    }

    CP_WAIT(0);
    __syncthreads();

    // -------- fused epilogue (bf16x3, unchanged) --------
    __nv_bfloat16* zwHi = (__nv_bfloat16*)(smem);
    __nv_bfloat16* zwLo = (__nv_bfloat16*)(smem + 6144);
    __nv_bfloat16* zbHi = (__nv_bfloat16*)(smem + 12288);
    __nv_bfloat16* zbLo = (__nv_bfloat16*)(smem + 18432);
    __nv_bfloat16* aWHi = (__nv_bfloat16*)(smem + 24576);
    __nv_bfloat16* aWLo = (__nv_bfloat16*)(smem + 36864);
    __nv_bfloat16* bWHi = (__nv_bfloat16*)(smem + 49152);
    __nv_bfloat16* bWLo = (__nv_bfloat16*)(smem + 61440);
    float* biasS = (float*)(smem + 73728);

    const int s = 4 * z + (n0 >> 10);
    const int hbase = n0 & 1023;

    if (tid < 128) {
        const __nv_bfloat16* sh = zwzbHiG + (size_t)(m0 + tid) * 256 + s * 16;
        const __nv_bfloat16* sl = zwzbLoG + (size_t)(m0 + tid) * 256 + s * 16;
        *(uint4*)((char*)zwHi + tid * 48)      = *(const uint4*)(sh);
        *(uint4*)((char*)zwHi + tid * 48 + 16) = *(const uint4*)(sh + 8);
        *(uint4*)((char*)zwLo + tid * 48)      = *(const uint4*)(sl);
        *(uint4*)((char*)zwLo + tid * 48 + 16) = *(const uint4*)(sl + 8);
        *(uint4*)((char*)zbHi + tid * 48)      = *(const uint4*)(sh + 128);
        *(uint4*)((char*)zbHi + tid * 48 + 16) = *(const uint4*)(sh + 136);
        *(uint4*)((char*)zbLo + tid * 48)      = *(const uint4*)(sl + 128);
        *(uint4*)((char*)zbLo + tid * 48 + 16) = *(const uint4*)(sl + 136);
    }
    {
        const int r = tid >> 1, half = tid & 1;
        const size_t go = ((size_t)s * 1024 + hbase + r) * 16;
        const __nv_bfloat16* asrc = (half ? aWLoG : aWHiG) + go;
        __nv_bfloat16* adst = half ? aWLo : aWHi;
        *(uint4*)((char*)adst + r * 48)      = *(const uint4*)(asrc);
        *(uint4*)((char*)adst + r * 48 + 16) = *(const uint4*)(asrc + 8);
        const __nv_bfloat16* bsrc = (half ? bWLoG : bWHiG) + go;
        __nv_bfloat16* bdst = half ? bWLo : bWHi;
        *(uint4*)((char*)bdst + r * 48)      = *(const uint4*)(bsrc);
        *(uint4*)((char*)bdst + r * 48 + 16) = *(const uint4*)(bsrc + 8);
    }
    if (tid < 256) biasS[tid] = (z ? bias1 : bias0)[n0 + tid];
    __syncthreads();

    const int rA = wm * 32 + (lane & 15);
    const uint32_t segOff = (lane >> 4) * 16;
    const int offB = (lane & 3) * 4;

    // ---- alpha ----
    {
        uint32_t fAh[2][4], fAl[2][4];
        #pragma unroll
        for (int mi = 0; mi < 2; ++mi) {
            const int row = rA + mi * 16;
            ldmat4(fAh[mi], sb + 0    + row * 48 + segOff);
            ldmat4(fAl[mi], sb + 6144 + row * 48 + segOff);
        }
        #pragma unroll
        for (int h = 0; h < 2; ++h) {
            float eacc[2][4][4];
            #pragma unroll
            for (int mi = 0; mi < 2; ++mi)
                #pragma unroll
                for (int nj = 0; nj < 4; ++nj)
                    #pragma unroll
                    for (int q = 0; q < 4; ++q) eacc[mi][nj][q] = 0.f;
            #pragma unroll
            for (int nj = 0; nj < 4; ++nj) {
                const int row = wn * 64 + (h * 4 + nj) * 8 + (lane >> 2);
                uint32_t bh[2], bl[2];
                bh[0] = *(const uint32_t*)((const char*)aWHi + row * 48 + offB);
                bh[1] = *(const uint32_t*)((const char*)aWHi + row * 48 + offB + 16);
                bl[0] = *(const uint32_t*)((const char*)aWLo + row * 48 + offB);
                bl[1] = *(const uint32_t*)((const char*)aWLo + row * 48 + offB + 16);
                #pragma unroll
                for (int mi = 0; mi < 2; ++mi) {
                    mma16816(eacc[mi][nj], fAh[mi], bh);
                    mma16816(eacc[mi][nj], fAh[mi], bl);
                    mma16816(eacc[mi][nj], fAl[mi], bh);
                }
            }
            #pragma unroll
            for (int mi = 0; mi < 2; ++mi)
                #pragma unroll
                for (int nj = 0; nj < 4; ++nj)
                    #pragma unroll
                    for (int q = 0; q < 4; ++q) acc[mi][h * 4 + nj][q] *= eacc[mi][nj][q];
        }
    }
    // ---- beta ----
    {
        uint32_t fAh[2][4], fAl[2][4];
        #pragma unroll
        for (int mi = 0; mi < 2; ++mi) {
            const int row = rA + mi * 16;
            ldmat4(fAh[mi], sb + 12288 + row * 48 + segOff);
            ldmat4(fAl[mi], sb + 18432 + row * 48 + segOff);
        }
        #pragma unroll
        for (int h = 0; h < 2; ++h) {
            float eacc[2][4][4];
            #pragma unroll
            for (int mi = 0; mi < 2; ++mi)
                #pragma unroll
                for (int nj = 0; nj < 4; ++nj)
                    #pragma unroll
                    for (int q = 0; q < 4; ++q) eacc[mi][nj][q] = 0.f;
            #pragma unroll
            for (int nj = 0; nj < 4; ++nj) {
                const int row = wn * 64 + (h * 4 + nj) * 8 + (lane >> 2);
                uint32_t bh[2], bl[2];
                bh[0] = *(const uint32_t*)((const char*)bWHi + row * 48 + offB);
                bh[1] = *(const uint32_t*)((const char*)bWHi + row * 48 + offB + 16);
                bl[0] = *(const uint32_t*)((const char*)bWLo + row * 48 + offB);
                bl[1] = *(const uint32_t*)((const char*)bWLo + row * 48 + offB + 16);
                #pragma unroll
                for (int mi = 0; mi < 2; ++mi) {
                    mma16816(eacc[mi][nj], fAh[mi], bh);
                    mma16816(eacc[mi][nj], fAh[mi], bl);
                    mma16816(eacc[mi][nj], fAl[mi], bh);
                }
            }
            #pragma unroll
            for (int mi = 0; mi < 2; ++mi)
                #pragma unroll
                for (int nj = 0; nj < 4; ++nj)
                    #pragma unroll
                    for (int q = 0; q < 4; ++q) acc[mi][h * 4 + nj][q] += eacc[mi][nj][q];
        }
    }

    #pragma unroll
    for (int mi = 0; mi < 2; ++mi) {
        const int row = m0 + wm * 32 + mi * 16 + (lane >> 2);
        #pragma unroll
        for (int ni = 0; ni < 8; ++ni) {
            const int cl = wn * 64 + ni * 8 + (lane & 3) * 2;
            const float b0 = biasS[cl], b1 = biasS[cl + 1];
            *(float2*)(C + (size_t)row * ldc + n0 + cl)       = make_float2(acc[mi][ni][0] + b0, acc[mi][ni][1] + b1);
            *(float2*)(C + (size_t)(row + 8) * ldc + n0 + cl) = make_float2(acc[mi][ni][2] + b0, acc[mi][ni][3] + b1);
        }
    }
}

// ================= ADAPTER GEMM fp16x2: 512 thr, tile 128x128, Kc=64, 3-stage =========
#define STG_AD 49152
#define SMEM_AD (3 * STG_AD)

__global__ __launch_bounds__(512, 1)
void gemm_adapter(const __half* __restrict__ A1hi, const __half* __restrict__ A1lo,
                  int lda1,
                  const __half* __restrict__ B1hi,
                  float* __restrict__ C1, int ldc1, int K1,
                  const __half* __restrict__ A2hi, const __half* __restrict__ A2lo,
                  int lda2,
                  const __half* __restrict__ B2hi,
                  float* __restrict__ C2, int ldc2, int K2)
{
    extern __shared__ char smem[];
    const uint32_t sb = smem_u32(smem);

    const int tid  = threadIdx.x;
    const int lane = tid & 31;
    const int wid  = tid >> 5;
    const int wm   = wid >> 2;
    const int wn   = wid & 3;
    const int m0 = blockIdx.y * 128;
    const int n0 = blockIdx.x * 128;

    const __half *Ahi, *Alo, *Bhi;
    float* C;
    int lda, ldc, K;
    if (blockIdx.z == 1) {
        Ahi = A2hi; Alo = A2lo; lda = lda2;
        Bhi = B2hi;
        C = C2; ldc = ldc2; K = K2;
    } else {
        Ahi = A1hi; Alo = A1lo; lda = lda1;
        Bhi = B1hi;
        C = C1; ldc = ldc1; K = K1;
    }

    float acc[2][4][4];
    #pragma unroll
    for (int i = 0; i < 2; i++)
        #pragma unroll
        for (int j = 0; j < 4; j++)
            #pragma unroll
            for (int q = 0; q < 4; q++) acc[i][j][q] = 0.f;

    const int nCh = K >> 6;
    const int ldRow = tid >> 3;
    const int ldSeg = tid & 7;

    auto load_stage = [&](int chunk, int buf) {
        const uint32_t sbase = sb + buf * STG_AD;
        const int kcol = chunk * 64;
        #pragma unroll
        for (int it = 0; it < 2; ++it) {
            const int row = ldRow + it * 64;
            const uint32_t so = (row << 7) + ((ldSeg ^ (row & 7)) << 4);
            const size_t ga = (size_t)(m0 + row) * lda + kcol + ldSeg * 8;
            cp_async16(sbase + so,         Ahi + ga);
            cp_async16(sbase + 16384 + so, Alo + ga);
            const size_t gb = (size_t)(n0 + row) * K + kcol + ldSeg * 8;
            cp_async16(sbase + 32768 + so, Bhi + gb);
        }
    };

    if (nCh > 0) load_stage(0, 0); CP_COMMIT();
    if (nCh > 1) load_stage(1, 1); CP_COMMIT();

    for (int c = 0; c < nCh; ++c) {
        CP_WAIT(1);
        __syncthreads();
        if (c + 2 < nCh) load_stage(c + 2, (c + 2) % 3);
        CP_COMMIT();

        const uint32_t aHiB = sb + (c % 3) * STG_AD;
        const uint32_t aLoB = aHiB + 16384;
        const uint32_t bHiB = aHiB + 32768;

        #pragma unroll
        for (int ks = 0; ks < 4; ++ks) {
            uint32_t ahi[2][4], alo[2][4];
            const int rA = wm * 32 + (lane & 15);
            const int segA = ks * 2 + (lane >> 4);
            #pragma unroll
            for (int mi = 0; mi < 2; ++mi) {
                const int row = rA + mi * 16;
                const uint32_t ad = (uint32_t)(row << 7) + (uint32_t)((segA ^ (row & 7)) << 4);
                ldmat4(ahi[mi], aHiB + ad);
                ldmat4(alo[mi], aLoB + ad);
            }
            uint32_t bhi[4][2];
            #pragma unroll
            for (int p = 0; p < 2; ++p) {
                const int mi2 = lane >> 3;
                const int row = wn * 32 + (p * 2 + (mi2 >> 1)) * 8 + (lane & 7);
                const int seg = ks * 2 + (mi2 & 1);
                const uint32_t ad = (uint32_t)(row << 7) + (uint32_t)((seg ^ (row & 7)) << 4);
                ldmat4(&bhi[p * 2][0], bHiB + ad);
            }
            #pragma unroll
            for (int mi = 0; mi < 2; ++mi)
                #pragma unroll
                for (int nj = 0; nj < 4; ++nj) {
                    mma16816h(acc[mi][nj], ahi[mi], bhi[nj]);
                    mma16816h(acc[mi][nj], alo[mi], bhi[nj]);
                }
        }
    }

    CP_WAIT(0);
    __syncthreads();

    #pragma unroll
    for (int mi = 0; mi < 2; ++mi) {
        const int row = m0 + wm * 32 + mi * 16 + (lane >> 2);
        #pragma unroll
        for (int ni = 0; ni < 4; ++ni) {
            const int cl = wn * 32 + ni * 8 + (lane & 3) * 2;
            *(float2*)(C + (size_t)row * ldc + n0 + cl)       = make_float2(acc[mi][ni][0], acc[mi][ni][1]);
            *(float2*)(C + (size_t)(row + 8) * ldc + n0 + cl) = make_float2(acc[mi][ni][2], acc[mi][ni][3]);
        }
    }
}

// ---------------- fused adapter pointwise + zwzb (v2: 16 rows/block) ------------------
__device__ __forceinline__ float sigf(float x) { return 1.f / (1.f + expf(-x)); }

__global__ __launch_bounds__(512)
void adapter_fused(const float* __restrict__ igpre, const float* __restrict__ hgpre,
                   const float* __restrict__ total_c,
                   const float* __restrict__ a_ln_i_w, const float* __restrict__ a_ln_i_b,
                   const float* __restrict__ a_ln_h_w, const float* __restrict__ a_ln_h_b,
                   const float* __restrict__ a_ln_c_w, const float* __restrict__ a_ln_c_b,
                   const float* __restrict__ nwT, const float* __restrict__ norm_zw_b,
                   __nv_bfloat16* __restrict__ zwzbHi, __nv_bfloat16* __restrict__ zwzbLo,
                   float* __restrict__ out, int writeFull)
{
    __shared__ float sada[16][128];
    const int w = threadIdx.x >> 5, lane = threadIdx.x & 31;
    const int b = blockIdx.x * 16 + w;

    float ig[4][4], hg[4][4];
    float s1i = 0.f, s2i = 0.f, s1h = 0.f, s2h = 0.f;
    #pragma unroll
    for (int k = 0; k < 4; ++k) {
        float4 v = *(const float4*)(igpre + (size_t)b * 512 + k * 128 + lane * 4);
        ig[k][0] = v.x; ig[k][1] = v.y; ig[k][2] = v.z; ig[k][3] = v.w;
        s1i += v.x + v.y + v.z + v.w;
        s2i += v.x * v.x + v.y * v.y + v.z * v.z + v.w * v.w;
        float4 u = *(const float4*)(hgpre + (size_t)b * 512 + k * 128 + lane * 4);
        hg[k][0] = u.x; hg[k][1] = u.y; hg[k][2] = u.z; hg[k][3] = u.w;
        s1h += u.x + u.y + u.z + u.w;
        s2h += u.x * u.x + u.y * u.y + u.z * u.z + u.w * u.w;
    }
    #pragma unroll
    for (int o = 16; o > 0; o >>= 1) {
        s1i += __shfl_xor_sync(0xffffffffu, s1i, o);
        s2i += __shfl_xor_sync(0xffffffffu, s2i, o);
        s1h += __shfl_xor_sync(0xffffffffu, s1h, o);
        s2h += __shfl_xor_sync(0xffffffffu, s2h, o);
    }
    const float muI = s1i * (1.f / 512.f);
    const float rsI = rsqrtf(s2i * (1.f / 512.f) - muI * muI + LN_EPS);
    const float muH = s1h * (1.f / 512.f);
    const float rsH = rsqrtf(s2h * (1.f / 512.f) - muH * muH + LN_EPS);

    float g[4][4];
    #pragma unroll
    for (int k = 0; k < 4; ++k) {
        float4 liw = *(const float4*)(a_ln_i_w + k * 128 + lane * 4);
        float4 lib = *(const float4*)(a_ln_i_b + k * 128 + lane * 4);
        float4 lhw = *(const float4*)(a_ln_h_w + k * 128 + lane * 4);
        float4 lhb = *(const float4*)(a_ln_h_b + k * 128 + lane * 4);
        const float* pw = &liw.x; const float* pb = &lib.x;
        const float* qw = &lhw.x; const float* qb = &lhb.x;
        #pragma unroll
        for (int q = 0; q < 4; ++q)
            g[k][q] = (ig[k][q] - muI) * rsI * pw[q] + pb[q]
                    + (hg[k][q] - muH) * rsH * qw[q] + qb[q];
    }

    float4 ac4 = *(const float4*)(total_c + (size_t)b * THW + 1024 + lane * 4);
    const float* acp = &ac4.x;
    float cpre[4];
    float sc = 0.f, sc2 = 0.f;
    #pragma unroll
    for (int q = 0; q < 4; ++q) {
        cpre[q] = sigf(g[1][q]) * acp[q] + sigf(g[0][q]) * tanhf(g[2][q]);
        sc += cpre[q]; sc2 += cpre[q] * cpre[q];
    }
    #pragma unroll
    for (int o = 16; o > 0; o >>= 1) {
        sc  += __shfl_xor_sync(0xffffffffu, sc, o);
        sc2 += __shfl_xor_sync(0xffffffffu, sc2, o);
    }
    const float mc = sc * (1.f / 128.f);
    const float rc = rsqrtf(sc2 * (1.f / 128.f) - mc * mc + LN_EPS);

    float4 lcw = *(const float4*)(a_ln_c_w + lane * 4);
    float4 lcb = *(const float4*)(a_ln_c_b + lane * 4);
    const float* cw = &lcw.x; const float* cb = &lcb.x;
    float acy[4], ada[4];
    #pragma unroll
    for (int q = 0; q < 4; ++q) {
        acy[q] = (cpre[q] - mc) * rc * cw[q] + cb[q];
        ada[q] = sigf(g[3][q]) * tanhf(acy[q]);
        sada[w][lane * 4 + q] = ada[q];
    }
    if (writeFull) {
        *(float4*)(out + OFF_H + (size_t)b * THW + 1024 + lane * 4) = make_float4(ada[0], ada[1], ada[2], ada[3]);
        *(float4*)(out + OFF_C + (size_t)b * THW + 1024 + lane * 4) = make_float4(acy[0], acy[1], acy[2], acy[3]);
    }
    __syncthreads();

    const int j = threadIdx.x & 255;
    const int rh = (threadIdx.x >> 8) * 8;
    float acc[8];
    #pragma unroll
    for (int r = 0; r < 8; ++r) acc[r] = 0.f;
    for (int a = 0; a < 128; ++a) {
        const float wv = __ldg(nwT + a * 256 + j);
        #pragma unroll
        for (int r = 0; r < 8; ++r) acc[r] += sada[rh + r][a] * wv;
    }
    const float zbias = (j < 128) ? norm_zw_b[j] : 0.f;
    const int b0 = blockIdx.x * 16 + rh;
    #pragma unroll
    for (int r = 0; r < 8; ++r) {
        float v = acc[r] + zbias;
        __nv_bfloat16 h = __float2bfloat16(v);
        zwzbHi[(size_t)(b0 + r) * 256 + j] = h;
        zwzbLo[(size_t)(b0 + r) * 256 + j] = __float2bfloat16(v - __bfloat162float(h));
    }
}

// ---------------- main pointwise (v2) ----------------
__device__ __forceinline__ void blockReduce4(float* v, int n, float* red, int t) {
    #pragma unroll
    for (int o = 16; o > 0; o >>= 1)
        for (int k = 0; k < 4; ++k) if (k < n) v[k] += __shfl_xor_sync(0xffffffffu, v[k], o);
    if ((t & 31) == 0)
        for (int k = 0; k < n; ++k) red[(t >> 5) * n + k] = v[k];
    __syncthreads();
    for (int k = 0; k < n; ++k) {
        float s = 0.f;
        for (int w = 0; w < 16; ++w) s += red[w * n + k];
        v[k] = s;
    }
    __syncthreads();
}

__global__ __launch_bounds__(512)
void main_pointwise(const float* __restrict__ ing, const float* __restrict__ hidg,
                    const float* __restrict__ total_c,
                    const float* __restrict__ ln_i_w, const float* __restrict__ ln_i_b,
                    const float* __restrict__ ln_h_w, const float* __restrict__ ln_h_b,
                    const float* __restrict__ ln_c_w, const float* __restrict__ ln_c_b,
                    float* __restrict__ out, int writeFull)
{
    __shared__ float sIn[4096];
    __shared__ float sHid[4096];
    __shared__ float red[64];
    const int b = blockIdx.x;
    const int t = threadIdx.x;

    const float4* pi = (const float4*)(ing  + (size_t)b * 4096);
    const float4* ph = (const float4*)(hidg + (size_t)b * 4096);
    float sums[4] = {0.f, 0.f, 0.f, 0.f};
    for (int i = t; i < 1024; i += 512) {
        float4 v = pi[i]; ((float4*)sIn)[i] = v;
        sums[0] += v.x + v.y + v.z + v.w;
        sums[1] += v.x * v.x + v.y * v.y + v.z * v.z + v.w * v.w;
        float4 u = ph[i]; ((float4*)sHid)[i] = u;
        sums[2] += u.x + u.y + u.z + u.w;
        sums[3] += u.x * u.x + u.y * u.y + u.z * u.z + u.w * u.w;
    }
    __syncthreads();
    blockReduce4(sums, 4, red, t);
    const float muI = sums[0] * (1.f / 4096.f);
    const float rsI = rsqrtf(sums[1] * (1.f / 4096.f) - muI * muI + LN_EPS);
    const float muH = sums[2] * (1.f / 4096.f);
    const float rsH = rsqrtf(sums[3] * (1.f / 4096.f) - muH * muH + LN_EPS);

    for (int i = t; i < 1024; i += 512) {
        float4 vi = ((float4*)sIn)[i];
        float4 vh = ((float4*)sHid)[i];
        float4 liw = ((const float4*)ln_i_w)[i];
        float4 lib = ((const float4*)ln_i_b)[i];
        float4 lhw = ((const float4*)ln_h_w)[i];
        float4 lhb = ((const float4*)ln_h_b)[i];
        float4 g;
        g.x = (vi.x - muI) * rsI * liw.x + lib.x + (vh.x - muH) * rsH * lhw.x + lhb.x;
        g.y = (vi.y - muI) * rsI * liw.y + lib.y + (vh.y - muH) * rsH * lhw.y + lhb.y;
        g.z = (vi.z - muI) * rsI * liw.z + lib.z + (vh.z - muH) * rsH * lhw.z + lhb.z;
        g.w = (vi.w - muI) * rsI * liw.w + lib.w + (vh.w - muH) * rsH * lhw.w + lhb.w;
        ((float4*)sIn)[i] = g;
    }
    __syncthreads();

    float cp[2], gov[2];
    float csum[4] = {0.f, 0.f, 0.f, 0.f};
    #pragma unroll
    for (int k = 0; k < 2; ++k) {
        const int h = t + k * 512;
        float gi = sIn[h], gj = sIn[1024 + h], gf = sIn[2048 + h], go = sIn[3072 + h];
        float cx = total_c[(size_t)b * THW + h];
        float c = sigf(gf) * cx + sigf(gi) * tanhf(gj);
        cp[k] = c; gov[k] = go;
        csum[0] += c; csum[1] += c * c;
    }
    blockReduce4(csum, 2, red, t);
    const float mc = csum[0] * (1.f / 1024.f);
    const float rc = rsqrtf(csum[1] * (1.f / 1024.f) - mc * mc + LN_EPS);

    #pragma unroll
    for (int k = 0; k < 2; ++k) {
        const int h = t + k * 512;
        float cy = (cp[k] - mc) * rc * ln_c_w[h] + ln_c_b[h];
        float hy = sigf(gov[k]) * tanhf(cy);
        out[(size_t)b * 1024 + h] = hy;
        if (writeFull) {
            out[OFF_H + (size_t)b * THW + h] = hy;
            out[OFF_C + (size_t)b * THW + h] = cy;
        }
    }
}

// ---------------- launch ----------------
extern "C" void kernel_launch(void* const* d_in, const int* in_sizes, int n_in,
                              void* d_out, int out_size)
{
    const float* x           = (const float*)d_in[0];
    const float* total_h     = (const float*)d_in[1];
    const float* total_c     = (const float*)d_in[2];
    const float* w_ih        = (const float*)d_in[3];
    const float* w_hh        = (const float*)d_in[4];
    const float* b_ih        = (const float*)d_in[5];
    const float* b_hh        = (const float*)d_in[6];
    const float* ln_i_w      = (const float*)d_in[7];
    const float* ln_i_b      = (const float*)d_in[8];
    const float* ln_h_w      = (const float*)d_in[9];
    const float* ln_h_b      = (const float*)d_in[10];
    const float* ln_c_w      = (const float*)d_in[11];
    const float* ln_c_b      = (const float*)d_in[12];
    const float* norm_zw_w   = (const float*)d_in[13];
    const float* norm_zw_b   = (const float*)d_in[14];
    const float* norm_alpha_w= (const float*)d_in[15];
    const float* bias_zb_w   = (const float*)d_in[16];
    const float* bias_beta_w = (const float*)d_in[17];
    const float* a_w_ih      = (const float*)d_in[18];
    const float* a_w_hh      = (const float*)d_in[19];
    const float* a_ln_i_w    = (const float*)d_in[20];
    const float* a_ln_i_b    = (const float*)d_in[21];
    const float* a_ln_h_w    = (const float*)d_in[22];
    const float* a_ln_h_b    = (const float*)d_in[23];
    const float* a_ln_c_w    = (const float*)d_in[24];
    const float* a_ln_c_b    = (const float*)d_in[25];
    float* out = (float*)d_out;

    const int writeFull = (size_t)out_size >= OUT_FULL_SIZE ? 1 : 0;

    __half *xh_hi, *xh_lo, *wm_hi, *awih_hi, *ah_hi, *ah_lo, *awhh_hi;
    __nv_bfloat16 *zwzbHi, *zwzbLo, *aWHi, *aWLo, *bWHi, *bWLo;
    float *igpre, *hgpre, *gates, *nwT;
    cudaGetSymbolAddress((void**)&xh_hi, g_xh_hi);     cudaGetSymbolAddress((void**)&xh_lo, g_xh_lo);
    cudaGetSymbolAddress((void**)&wm_hi, g_wm_hi);
    cudaGetSymbolAddress((void**)&awih_hi, g_awih_hi);
    cudaGetSymbolAddress((void**)&ah_hi, g_ah_hi);     cudaGetSymbolAddress((void**)&ah_lo, g_ah_lo);
    cudaGetSymbolAddress((void**)&awhh_hi, g_awhh_hi);
    cudaGetSymbolAddress((void**)&zwzbHi, g_zwzbHi);   cudaGetSymbolAddress((void**)&zwzbLo, g_zwzbLo);
    cudaGetSymbolAddress((void**)&aWHi, g_aWHi);       cudaGetSymbolAddress((void**)&aWLo, g_aWLo);
    cudaGetSymbolAddress((void**)&bWHi, g_bWHi);       cudaGetSymbolAddress((void**)&bWLo, g_bWLo);
    cudaGetSymbolAddress((void**)&nwT, g_nwT);
    cudaGetSymbolAddress((void**)&igpre, g_igpre);     cudaGetSymbolAddress((void**)&hgpre, g_hgpre);
    cudaGetSymbolAddress((void**)&gates, g_gates);

    cudaFuncSetAttribute(gemm_main,    cudaFuncAttributeMaxDynamicSharedMemorySize, SMEM_MAIN);
    cudaFuncSetAttribute(gemm_adapter, cudaFuncAttributeMaxDynamicSharedMemorySize, SMEM_AD);

    // 0: all conversions
    split_all<<<9248, 256>>>(w_ih, w_hh, x, total_h, a_w_ih, a_w_hh,
                             norm_alpha_w, bias_beta_w, norm_zw_w, bias_zb_w,
                             wm_hi, xh_hi, xh_lo, ah_hi, ah_lo,
                             awih_hi, awhh_hi,
                             aWHi, aWLo, bWHi, bWLo, nwT);

    // 1: adapter GEMMs (dual, fp16x2)
    gemm_adapter<<<dim3(4, 32, 2), 512, SMEM_AD>>>(
        xh_hi, xh_lo, 2048, awih_hi, igpre, 512, 2048,
        ah_hi, ah_lo, 128, awhh_hi, hgpre, 512, 128);

    // 2: adapter pointwise + zwzb fused
    adapter_fused<<<Bsz / 16, 512>>>(
        igpre, hgpre, total_c,
        a_ln_i_w, a_ln_i_b, a_ln_h_w, a_ln_h_b, a_ln_c_w, a_ln_c_b,
        nwT, norm_zw_b, zwzbHi, zwzbLo, out, writeFull);

    // 3: main GEMMs (fp16x2, 3-stage single-sync) + fused alpha/beta epilogue
    gemm_main<<<dim3(16, 32, 2), 512, SMEM_MAIN>>>(
        xh_hi, xh_lo, 2048, 1024, wm_hi, (long)4096 * 1024,
        gates, 4096, (long)4096 * 4096, 1024,
        zwzbHi, zwzbLo, aWHi, aWLo, bWHi, bWLo, b_ih, b_hh);

    // 4: main pointwise (v2)
    main_pointwise<<<Bsz, 512>>>(
        gates, gates + (size_t)4096 * 4096, total_c,
        ln_i_w, ln_i_b, ln_h_w, ln_h_b, ln_c_w, ln_c_b,
        out, writeFull);
}

// round 17
// speedup vs baseline: 1.0082x; 1.0082x over previous
#include <cuda_runtime.h>
#include <cuda_bf16.h>
#include <cuda_fp16.h>
#include <math.h>
#include <stdint.h>

#define Bsz   4096
#define THW   1152
#define LN_EPS 1e-5f

#define OFF_H ((size_t)Bsz * 1024)
#define OFF_C (OFF_H + (size_t)Bsz * THW)
#define OUT_FULL_SIZE (OFF_C + (size_t)Bsz * THW)

// ---------------- scratch ----------------
__device__ __half g_xh_hi[(size_t)Bsz * 2048];
__device__ __half g_xh_lo[(size_t)Bsz * 2048];
__device__ __half g_wm_hi[(size_t)2 * 4096 * 1024];
__device__ __half g_awih_hi[(size_t)512 * 2048];
__device__ __half g_ah_hi[(size_t)Bsz * 128];
__device__ __half g_ah_lo[(size_t)Bsz * 128];
__device__ __half g_awhh_hi[(size_t)512 * 128];
__device__ __nv_bfloat16 g_zwzbHi[(size_t)Bsz * 256];
__device__ __nv_bfloat16 g_zwzbLo[(size_t)Bsz * 256];
__device__ __nv_bfloat16 g_aWHi[131072];
__device__ __nv_bfloat16 g_aWLo[131072];
__device__ __nv_bfloat16 g_bWHi[131072];
__device__ __nv_bfloat16 g_bWLo[131072];
__device__ float g_nwT[128 * 256];
__device__ float g_igpre[(size_t)Bsz * 512];
__device__ float g_hgpre[(size_t)Bsz * 512];
__device__ __half g_gates[(size_t)2 * Bsz * 4096];   // fp16 intermediate (halved traffic)

// ---------------- PTX helpers ----------------
__device__ __forceinline__ uint32_t smem_u32(const void* p) {
    uint32_t a;
    asm("{ .reg .u64 t; cvta.to.shared.u64 t, %1; cvt.u32.u64 %0, t; }" : "=r"(a) : "l"(p));
    return a;
}
__device__ __forceinline__ void cp_async16(uint32_t smaddr, const void* gaddr) {
    asm volatile("cp.async.cg.shared.global [%0], [%1], 16;" :: "r"(smaddr), "l"(gaddr) : "memory");
}
#define CP_COMMIT() asm volatile("cp.async.commit_group;" ::: "memory")
#define CP_WAIT(n)  asm volatile("cp.async.wait_group %0;" :: "n"(n) : "memory")

__device__ __forceinline__ void ldmat4(uint32_t* r, uint32_t addr) {
    asm volatile("ldmatrix.sync.aligned.m8n8.x4.shared.b16 {%0,%1,%2,%3}, [%4];"
        : "=r"(r[0]), "=r"(r[1]), "=r"(r[2]), "=r"(r[3]) : "r"(addr));
}
__device__ __forceinline__ void mma16816(float* c, const uint32_t* a, const uint32_t* b) {
    asm volatile("mma.sync.aligned.m16n8k16.row.col.f32.bf16.bf16.f32 "
        "{%0,%1,%2,%3}, {%4,%5,%6,%7}, {%8,%9}, {%0,%1,%2,%3};"
        : "+f"(c[0]), "+f"(c[1]), "+f"(c[2]), "+f"(c[3])
        : "r"(a[0]), "r"(a[1]), "r"(a[2]), "r"(a[3]), "r"(b[0]), "r"(b[1]));
}
__device__ __forceinline__ void mma16816h(float* c, const uint32_t* a, const uint32_t* b) {
    asm volatile("mma.sync.aligned.m16n8k16.row.col.f32.f16.f16.f32 "
        "{%0,%1,%2,%3}, {%4,%5,%6,%7}, {%8,%9}, {%0,%1,%2,%3};"
        : "+f"(c[0]), "+f"(c[1]), "+f"(c[2]), "+f"(c[3])
        : "r"(a[0]), "r"(a[1]), "r"(a[2]), "r"(a[3]), "r"(b[0]), "r"(b[1]));
}

// ---------------- conversions ----------------
__device__ __forceinline__ void splitA16(const float* src, int srcLd,
                                         __half* hi, __half* lo,
                                         int dstLd, int w8, int idx)
{
    const int r = idx / w8, c = (idx - r * w8) * 8;
    const float* s = src + (size_t)r * srcLd + c;
    float4 v0 = *(const float4*)s;
    float4 v1 = *(const float4*)(s + 4);
    float f[8] = { v0.x, v0.y, v0.z, v0.w, v1.x, v1.y, v1.z, v1.w };
    __half h[8], l[8];
    #pragma unroll
    for (int i = 0; i < 8; ++i) {
        h[i] = __float2half_rn(f[i]);
        l[i] = __float2half_rn(f[i] - __half2float(h[i]));
    }
    *(uint4*)(hi + (size_t)r * dstLd + c) = *(uint4*)h;
    *(uint4*)(lo + (size_t)r * dstLd + c) = *(uint4*)l;
}
__device__ __forceinline__ void cvtB16(const float* src, int srcLd,
                                       __half* hi, int dstLd, int w8, int idx)
{
    const int r = idx / w8, c = (idx - r * w8) * 8;
    const float* s = src + (size_t)r * srcLd + c;
    float4 v0 = *(const float4*)s;
    float4 v1 = *(const float4*)(s + 4);
    float f[8] = { v0.x, v0.y, v0.z, v0.w, v1.x, v1.y, v1.z, v1.w };
    __half h[8];
    #pragma unroll
    for (int i = 0; i < 8; ++i) h[i] = __float2half_rn(f[i]);
    *(uint4*)(hi + (size_t)r * dstLd + c) = *(uint4*)h;
}
__device__ __forceinline__ void splitBF(const float* src, int srcLd,
                                        __nv_bfloat16* hi, __nv_bfloat16* lo,
                                        int dstLd, int w8, int idx)
{
    const int r = idx / w8, c = (idx - r * w8) * 8;
    const float* s = src + (size_t)r * srcLd + c;
    float4 v0 = *(const float4*)s;
    float4 v1 = *(const float4*)(s + 4);
    float f[8] = { v0.x, v0.y, v0.z, v0.w, v1.x, v1.y, v1.z, v1.w };
    __nv_bfloat16 h[8], l[8];
    #pragma unroll
    for (int i = 0; i < 8; ++i) {
        h[i] = __float2bfloat16(f[i]);
        l[i] = __float2bfloat16(f[i] - __bfloat162float(h[i]));
    }
    *(uint4*)(hi + (size_t)r * dstLd + c) = *(uint4*)h;
    *(uint4*)(lo + (size_t)r * dstLd + c) = *(uint4*)l;
}

__global__ __launch_bounds__(256)
void split_all(const float* __restrict__ w_ih, const float* __restrict__ w_hh,
               const float* __restrict__ x, const float* __restrict__ total_h,
               const float* __restrict__ a_w_ih, const float* __restrict__ a_w_hh,
               const float* __restrict__ norm_alpha_w, const float* __restrict__ bias_beta_w,
               const float* __restrict__ norm_zw_w, const float* __restrict__ bias_zb_w,
               __half* __restrict__ wm_hi,
               __half* __restrict__ xh_hi, __half* __restrict__ xh_lo,
               __half* __restrict__ ah_hi, __half* __restrict__ ah_lo,
               __half* __restrict__ awih_hi, __half* __restrict__ awhh_hi,
               __nv_bfloat16* __restrict__ aWHi, __nv_bfloat16* __restrict__ aWLo,
               __nv_bfloat16* __restrict__ bWHi, __nv_bfloat16* __restrict__ bWLo,
               float* __restrict__ nwT)
{
    const int blk = blockIdx.x;
    const int t = threadIdx.x;
    if (blk < 2048)       cvtB16(w_ih, 1024, wm_hi, 1024, 128, blk * 256 + t);
    else if (blk < 4096)  cvtB16(w_hh, 1024, wm_hi + (size_t)4096 * 1024, 1024, 128, (blk - 2048) * 256 + t);
    else if (blk < 6144)  splitA16(x, 1024, xh_hi, xh_lo, 2048, 128, (blk - 4096) * 256 + t);
    else if (blk < 8192)  splitA16(total_h, THW, xh_hi + 1024, xh_lo + 1024, 2048, 128, (blk - 6144) * 256 + t);
    else if (blk < 8448)  splitA16(total_h + 1024, THW, ah_hi, ah_lo, 128, 16, (blk - 8192) * 256 + t);
    else if (blk < 8960)  cvtB16(a_w_ih, 2048, awih_hi, 2048, 256, (blk - 8448) * 256 + t);
    else if (blk < 8992)  cvtB16(a_w_hh, 128, awhh_hi, 128, 16, (blk - 8960) * 256 + t);
    else if (blk < 9056)  splitBF(norm_alpha_w, 131072, aWHi, aWLo, 131072, 16384, (blk - 8992) * 256 + t);
    else if (blk < 9120)  splitBF(bias_beta_w, 131072, bWHi, bWLo, 131072, 16384, (blk - 9056) * 256 + t);
    else {
        int idx = (blk - 9120) * 256 + t;
        int a = idx >> 8, j = idx & 255;
        nwT[a * 256 + j] = (j < 128) ? norm_zw_w[j * 128 + a] : bias_zb_w[(j - 128) * 128 + a];
    }
}

// ================= MAIN GEMM fp16x2 (R15 config): 512 thr, 128x256, Kc=64, 2-stage ====
#define STG_MAIN 65536
#define SMEM_MAIN (2 * STG_MAIN)

__global__ __launch_bounds__(512, 1)
void gemm_main(const __half* __restrict__ Ahi_, const __half* __restrict__ Alo_,
               int lda, int aZoff,
               const __half* __restrict__ Bhi_, long bZ,
               __half* __restrict__ C_, int ldc, long cZ, int K,
               const __nv_bfloat16* __restrict__ zwzbHiG, const __nv_bfloat16* __restrict__ zwzbLoG,
               const __nv_bfloat16* __restrict__ aWHiG, const __nv_bfloat16* __restrict__ aWLoG,
               const __nv_bfloat16* __restrict__ bWHiG, const __nv_bfloat16* __restrict__ bWLoG,
               const float* __restrict__ bias0, const float* __restrict__ bias1)
{
    extern __shared__ char smem[];
    const uint32_t sb = smem_u32(smem);

    const int tid  = threadIdx.x;
    const int lane = tid & 31;
    const int wid  = tid >> 5;
    const int wm   = wid >> 2;
    const int wn   = wid & 3;
    const int m0 = blockIdx.y * 128;
    const int n0 = blockIdx.x * 256;
    const int z  = blockIdx.z;

    const __half* Ahi = Ahi_ + (size_t)z * aZoff;
    const __half* Alo = Alo_ + (size_t)z * aZoff;
    const __half* Bhi = Bhi_ + (size_t)z * bZ;
    __half* C = C_ + (size_t)z * cZ;

    float acc[2][8][4];
    #pragma unroll
    for (int i = 0; i < 2; i++)
        #pragma unroll
        for (int j = 0; j < 8; j++)
            #pragma unroll
            for (int q = 0; q < 4; q++) acc[i][j][q] = 0.f;

    const int nCh = K >> 6;
    const int ldRow = tid >> 3;
    const int ldSeg = tid & 7;

    auto load_stage = [&](int chunk, int buf) {
        const uint32_t sbase = sb + buf * STG_MAIN;
        const int kcol = chunk * 64;
        #pragma unroll
        for (int it = 0; it < 2; ++it) {
            const int row = ldRow + it * 64;
            const uint32_t so = (row << 7) + ((ldSeg ^ (row & 7)) << 4);
            const size_t ga = (size_t)(m0 + row) * lda + kcol + ldSeg * 8;
            cp_async16(sbase + so,         Ahi + ga);
            cp_async16(sbase + 16384 + so, Alo + ga);
        }
        #pragma unroll
        for (int it = 0; it < 4; ++it) {
            const int row = ldRow + it * 64;
            const uint32_t so = (row << 7) + ((ldSeg ^ (row & 7)) << 4);
            const size_t gb = (size_t)(n0 + row) * K + kcol + ldSeg * 8;
            cp_async16(sbase + 32768 + so, Bhi + gb);
        }
    };

    load_stage(0, 0); CP_COMMIT();
    load_stage(1, 1); CP_COMMIT();

    for (int c = 0; c < nCh; ++c) {
        CP_WAIT(1);
        __syncthreads();

        const int buf = c & 1;
        const uint32_t aHiB = sb + buf * STG_MAIN;
        const uint32_t aLoB = aHiB + 16384;
        const uint32_t bHiB = aHiB + 32768;

        #pragma unroll
        for (int ks = 0; ks < 4; ++ks) {
            uint32_t ahi[2][4], alo[2][4];
            const int rA = wm * 32 + (lane & 15);
            #pragma unroll
            for (int mi = 0; mi < 2; ++mi) {
                const int row = rA + mi * 16;
                const uint32_t ad = (uint32_t)(row << 7) + (uint32_t)((((ks * 2) + (lane >> 4)) ^ (row & 7)) << 4);
                ldmat4(ahi[mi], aHiB + ad);
                ldmat4(alo[mi], aLoB + ad);
            }
            #pragma unroll
            for (int h = 0; h < 2; ++h) {
                uint32_t bhi[4][2];
                #pragma unroll
                for (int p = 0; p < 2; ++p) {
                    const int P = h * 2 + p;
                    const int mi2 = lane >> 3;
                    const int row = wn * 64 + (P * 2 + (mi2 >> 1)) * 8 + (lane & 7);
                    const uint32_t ad = (uint32_t)(row << 7) + (uint32_t)((((ks * 2) + (mi2 & 1)) ^ (row & 7)) << 4);
                    ldmat4(&bhi[p * 2][0], bHiB + ad);
                }
                #pragma unroll
                for (int mi = 0; mi < 2; ++mi)
                    #pragma unroll
                    for (int nj = 0; nj < 4; ++nj) {
                        mma16816h(acc[mi][h * 4 + nj], ahi[mi], bhi[nj]);
                        mma16816h(acc[mi][h * 4 + nj], alo[mi], bhi[nj]);
                    }
            }
        }
        __syncthreads();
        if (c + 2 < nCh) load_stage(c + 2, buf);
        CP_COMMIT();
    }

    CP_WAIT(0);
    __syncthreads();

    // -------- fused epilogue (bf16x3) --------
    __nv_bfloat16* zwHi = (__nv_bfloat16*)(smem);
    __nv_bfloat16* zwLo = (__nv_bfloat16*)(smem + 6144);
    __nv_bfloat16* zbHi = (__nv_bfloat16*)(smem + 12288);
    __nv_bfloat16* zbLo = (__nv_bfloat16*)(smem + 18432);
    __nv_bfloat16* aWHi = (__nv_bfloat16*)(smem + 24576);
    __nv_bfloat16* aWLo = (__nv_bfloat16*)(smem + 36864);
    __nv_bfloat16* bWHi = (__nv_bfloat16*)(smem + 49152);
    __nv_bfloat16* bWLo = (__nv_bfloat16*)(smem + 61440);
    float* biasS = (float*)(smem + 73728);

    const int s = 4 * z + (n0 >> 10);
    const int hbase = n0 & 1023;

    if (tid < 128) {
        const __nv_bfloat16* sh = zwzbHiG + (size_t)(m0 + tid) * 256 + s * 16;
        const __nv_bfloat16* sl = zwzbLoG + (size_t)(m0 + tid) * 256 + s * 16;
        *(uint4*)((char*)zwHi + tid * 48)      = *(const uint4*)(sh);
        *(uint4*)((char*)zwHi + tid * 48 + 16) = *(const uint4*)(sh + 8);
        *(uint4*)((char*)zwLo + tid * 48)      = *(const uint4*)(sl);
        *(uint4*)((char*)zwLo + tid * 48 + 16) = *(const uint4*)(sl + 8);
        *(uint4*)((char*)zbHi + tid * 48)      = *(const uint4*)(sh + 128);
        *(uint4*)((char*)zbHi + tid * 48 + 16) = *(const uint4*)(sh + 136);
        *(uint4*)((char*)zbLo + tid * 48)      = *(const uint4*)(sl + 128);
        *(uint4*)((char*)zbLo + tid * 48 + 16) = *(const uint4*)(sl + 136);
    }
    {
        const int r = tid >> 1, half = tid & 1;
        const size_t go = ((size_t)s * 1024 + hbase + r) * 16;
        const __nv_bfloat16* asrc = (half ? aWLoG : aWHiG) + go;
        __nv_bfloat16* adst = half ? aWLo : aWHi;
        *(uint4*)((char*)adst + r * 48)      = *(const uint4*)(asrc);
        *(uint4*)((char*)adst + r * 48 + 16) = *(const uint4*)(asrc + 8);
        const __nv_bfloat16* bsrc = (half ? bWLoG : bWHiG) + go;
        __nv_bfloat16* bdst = half ? bWLo : bWHi;
        *(uint4*)((char*)bdst + r * 48)      = *(const uint4*)(bsrc);
        *(uint4*)((char*)bdst + r * 48 + 16) = *(const uint4*)(bsrc + 8);
    }
    if (tid < 256) biasS[tid] = (z ? bias1 : bias0)[n0 + tid];
    __syncthreads();

    const int rA = wm * 32 + (lane & 15);
    const uint32_t segOff = (lane >> 4) * 16;
    const int offB = (lane & 3) * 4;

    // ---- alpha ----
    {
        uint32_t fAh[2][4], fAl[2][4];
        #pragma unroll
        for (int mi = 0; mi < 2; ++mi) {
            const int row = rA + mi * 16;
            ldmat4(fAh[mi], sb + 0    + row * 48 + segOff);
            ldmat4(fAl[mi], sb + 6144 + row * 48 + segOff);
        }
        #pragma unroll
        for (int h = 0; h < 2; ++h) {
            float eacc[2][4][4];
            #pragma unroll
            for (int mi = 0; mi < 2; ++mi)
                #pragma unroll
                for (int nj = 0; nj < 4; ++nj)
                    #pragma unroll
                    for (int q = 0; q < 4; ++q) eacc[mi][nj][q] = 0.f;
            #pragma unroll
            for (int nj = 0; nj < 4; ++nj) {
                const int row = wn * 64 + (h * 4 + nj) * 8 + (lane >> 2);
                uint32_t bh[2], bl[2];
                bh[0] = *(const uint32_t*)((const char*)aWHi + row * 48 + offB);
                bh[1] = *(const uint32_t*)((const char*)aWHi + row * 48 + offB + 16);
                bl[0] = *(const uint32_t*)((const char*)aWLo + row * 48 + offB);
                bl[1] = *(const uint32_t*)((const char*)aWLo + row * 48 + offB + 16);
                #pragma unroll
                for (int mi = 0; mi < 2; ++mi) {
                    mma16816(eacc[mi][nj], fAh[mi], bh);
                    mma16816(eacc[mi][nj], fAh[mi], bl);
                    mma16816(eacc[mi][nj], fAl[mi], bh);
                }
            }
            #pragma unroll
            for (int mi = 0; mi < 2; ++mi)
                #pragma unroll
                for (int nj = 0; nj < 4; ++nj)
                    #pragma unroll
                    for (int q = 0; q < 4; ++q) acc[mi][h * 4 + nj][q] *= eacc[mi][nj][q];
        }
    }
    // ---- beta ----
    {
        uint32_t fAh[2][4], fAl[2][4];
        #pragma unroll
        for (int mi = 0; mi < 2; ++mi) {
            const int row = rA + mi * 16;
            ldmat4(fAh[mi], sb + 12288 + row * 48 + segOff);
            ldmat4(fAl[mi], sb + 18432 + row * 48 + segOff);
        }
        #pragma unroll
        for (int h = 0; h < 2; ++h) {
            float eacc[2][4][4];
            #pragma unroll
            for (int mi = 0; mi < 2; ++mi)
                #pragma unroll
                for (int nj = 0; nj < 4; ++nj)
                    #pragma unroll
                    for (int q = 0; q < 4; ++q) eacc[mi][nj][q] = 0.f;
            #pragma unroll
            for (int nj = 0; nj < 4; ++nj) {
                const int row = wn * 64 + (h * 4 + nj) * 8 + (lane >> 2);
                uint32_t bh[2], bl[2];
                bh[0] = *(const uint32_t*)((const char*)bWHi + row * 48 + offB);
                bh[1] = *(const uint32_t*)((const char*)bWHi + row * 48 + offB + 16);
                bl[0] = *(const uint32_t*)((const char*)bWLo + row * 48 + offB);
                bl[1] = *(const uint32_t*)((const char*)bWLo + row * 48 + offB + 16);
                #pragma unroll
                for (int mi = 0; mi < 2; ++mi) {
                    mma16816(eacc[mi][nj], fAh[mi], bh);
                    mma16816(eacc[mi][nj], fAh[mi], bl);
                    mma16816(eacc[mi][nj], fAl[mi], bh);
                }
            }
            #pragma unroll
            for (int mi = 0; mi < 2; ++mi)
                #pragma unroll
                for (int nj = 0; nj < 4; ++nj)
                    #pragma unroll
                    for (int q = 0; q < 4; ++q) acc[mi][h * 4 + nj][q] += eacc[mi][nj][q];
        }
    }

    // store as fp16
    #pragma unroll
    for (int mi = 0; mi < 2; ++mi) {
        const int row = m0 + wm * 32 + mi * 16 + (lane >> 2);
        #pragma unroll
        for (int ni = 0; ni < 8; ++ni) {
            const int cl = wn * 64 + ni * 8 + (lane & 3) * 2;
            const float b0 = biasS[cl], b1 = biasS[cl + 1];
            __half2 v0 = __floats2half2_rn(acc[mi][ni][0] + b0, acc[mi][ni][1] + b1);
            __half2 v1 = __floats2half2_rn(acc[mi][ni][2] + b0, acc[mi][ni][3] + b1);
            *(__half2*)(C + (size_t)row * ldc + n0 + cl)       = v0;
            *(__half2*)(C + (size_t)(row + 8) * ldc + n0 + cl) = v1;
        }
    }
}

// ================= ADAPTER GEMM fp16x2: 512 thr, 128x128, Kc=64, 3-stage ==============
#define STG_AD 49152
#define SMEM_AD (3 * STG_AD)

__global__ __launch_bounds__(512, 1)
void gemm_adapter(const __half* __restrict__ A1hi, const __half* __restrict__ A1lo,
                  int lda1,
                  const __half* __restrict__ B1hi,
                  float* __restrict__ C1, int ldc1, int K1,
                  const __half* __restrict__ A2hi, const __half* __restrict__ A2lo,
                  int lda2,
                  const __half* __restrict__ B2hi,
                  float* __restrict__ C2, int ldc2, int K2)
{
    extern __shared__ char smem[];
    const uint32_t sb = smem_u32(smem);

    const int tid  = threadIdx.x;
    const int lane = tid & 31;
    const int wid  = tid >> 5;
    const int wm   = wid >> 2;
    const int wn   = wid & 3;
    const int m0 = blockIdx.y * 128;
    const int n0 = blockIdx.x * 128;

    const __half *Ahi, *Alo, *Bhi;
    float* C;
    int lda, ldc, K;
    if (blockIdx.z == 1) {
        Ahi = A2hi; Alo = A2lo; lda = lda2;
        Bhi = B2hi;
        C = C2; ldc = ldc2; K = K2;
    } else {
        Ahi = A1hi; Alo = A1lo; lda = lda1;
        Bhi = B1hi;
        C = C1; ldc = ldc1; K = K1;
    }

    float acc[2][4][4];
    #pragma unroll
    for (int i = 0; i < 2; i++)
        #pragma unroll
        for (int j = 0; j < 4; j++)
            #pragma unroll
            for (int q = 0; q < 4; q++) acc[i][j][q] = 0.f;

    const int nCh = K >> 6;
    const int ldRow = tid >> 3;
    const int ldSeg = tid & 7;

    auto load_stage = [&](int chunk, int buf) {
        const uint32_t sbase = sb + buf * STG_AD;
        const int kcol = chunk * 64;
        #pragma unroll
        for (int it = 0; it < 2; ++it) {
            const int row = ldRow + it * 64;
            const uint32_t so = (row << 7) + ((ldSeg ^ (row & 7)) << 4);
            const size_t ga = (size_t)(m0 + row) * lda + kcol + ldSeg * 8;
            cp_async16(sbase + so,         Ahi + ga);
            cp_async16(sbase + 16384 + so, Alo + ga);
            const size_t gb = (size_t)(n0 + row) * K + kcol + ldSeg * 8;
            cp_async16(sbase + 32768 + so, Bhi + gb);
        }
    };

    if (nCh > 0) load_stage(0, 0); CP_COMMIT();
    if (nCh > 1) load_stage(1, 1); CP_COMMIT();

    for (int c = 0; c < nCh; ++c) {
        CP_WAIT(1);
        __syncthreads();
        if (c + 2 < nCh) load_stage(c + 2, (c + 2) % 3);
        CP_COMMIT();

        const uint32_t aHiB = sb + (c % 3) * STG_AD;
        const uint32_t aLoB = aHiB + 16384;
        const uint32_t bHiB = aHiB + 32768;

        #pragma unroll
        for (int ks = 0; ks < 4; ++ks) {
            uint32_t ahi[2][4], alo[2][4];
            const int rA = wm * 32 + (lane & 15);
            const int segA = ks * 2 + (lane >> 4);
            #pragma unroll
            for (int mi = 0; mi < 2; ++mi) {
                const int row = rA + mi * 16;
                const uint32_t ad = (uint32_t)(row << 7) + (uint32_t)((segA ^ (row & 7)) << 4);
                ldmat4(ahi[mi], aHiB + ad);
                ldmat4(alo[mi], aLoB + ad);
            }
            uint32_t bhi[4][2];
            #pragma unroll
            for (int p = 0; p < 2; ++p) {
                const int mi2 = lane >> 3;
                const int row = wn * 32 + (p * 2 + (mi2 >> 1)) * 8 + (lane & 7);
                const int seg = ks * 2 + (mi2 & 1);
                const uint32_t ad = (uint32_t)(row << 7) + (uint32_t)((seg ^ (row & 7)) << 4);
                ldmat4(&bhi[p * 2][0], bHiB + ad);
            }
            #pragma unroll
            for (int mi = 0; mi < 2; ++mi)
                #pragma unroll
                for (int nj = 0; nj < 4; ++nj) {
                    mma16816h(acc[mi][nj], ahi[mi], bhi[nj]);
                    mma16816h(acc[mi][nj], alo[mi], bhi[nj]);
                }
        }
    }

    CP_WAIT(0);
    __syncthreads();

    #pragma unroll
    for (int mi = 0; mi < 2; ++mi) {
        const int row = m0 + wm * 32 + mi * 16 + (lane >> 2);
        #pragma unroll
        for (int ni = 0; ni < 4; ++ni) {
            const int cl = wn * 32 + ni * 8 + (lane & 3) * 2;
            *(float2*)(C + (size_t)row * ldc + n0 + cl)       = make_float2(acc[mi][ni][0], acc[mi][ni][1]);
            *(float2*)(C + (size_t)(row + 8) * ldc + n0 + cl) = make_float2(acc[mi][ni][2], acc[mi][ni][3]);
        }
    }
}

// ---------------- fused adapter pointwise + zwzb (v2: 16 rows/block) ------------------
__device__ __forceinline__ float sigf(float x) { return 1.f / (1.f + expf(-x)); }

__global__ __launch_bounds__(512)
void adapter_fused(const float* __restrict__ igpre, const float* __restrict__ hgpre,
                   const float* __restrict__ total_c,
                   const float* __restrict__ a_ln_i_w, const float* __restrict__ a_ln_i_b,
                   const float* __restrict__ a_ln_h_w, const float* __restrict__ a_ln_h_b,
                   const float* __restrict__ a_ln_c_w, const float* __restrict__ a_ln_c_b,
                   const float* __restrict__ nwT, const float* __restrict__ norm_zw_b,
                   __nv_bfloat16* __restrict__ zwzbHi, __nv_bfloat16* __restrict__ zwzbLo,
                   float* __restrict__ out, int writeFull)
{
    __shared__ float sada[16][128];
    const int w = threadIdx.x >> 5, lane = threadIdx.x & 31;
    const int b = blockIdx.x * 16 + w;

    float ig[4][4], hg[4][4];
    float s1i = 0.f, s2i = 0.f, s1h = 0.f, s2h = 0.f;
    #pragma unroll
    for (int k = 0; k < 4; ++k) {
        float4 v = *(const float4*)(igpre + (size_t)b * 512 + k * 128 + lane * 4);
        ig[k][0] = v.x; ig[k][1] = v.y; ig[k][2] = v.z; ig[k][3] = v.w;
        s1i += v.x + v.y + v.z + v.w;
        s2i += v.x * v.x + v.y * v.y + v.z * v.z + v.w * v.w;
        float4 u = *(const float4*)(hgpre + (size_t)b * 512 + k * 128 + lane * 4);
        hg[k][0] = u.x; hg[k][1] = u.y; hg[k][2] = u.z; hg[k][3] = u.w;
        s1h += u.x + u.y + u.z + u.w;
        s2h += u.x * u.x + u.y * u.y + u.z * u.z + u.w * u.w;
    }
    #pragma unroll
    for (int o = 16; o > 0; o >>= 1) {
        s1i += __shfl_xor_sync(0xffffffffu, s1i, o);
        s2i += __shfl_xor_sync(0xffffffffu, s2i, o);
        s1h += __shfl_xor_sync(0xffffffffu, s1h, o);
        s2h += __shfl_xor_sync(0xffffffffu, s2h, o);
    }
    const float muI = s1i * (1.f / 512.f);
    const float rsI = rsqrtf(s2i * (1.f / 512.f) - muI * muI + LN_EPS);
    const float muH = s1h * (1.f / 512.f);
    const float rsH = rsqrtf(s2h * (1.f / 512.f) - muH * muH + LN_EPS);

    float g[4][4];
    #pragma unroll
    for (int k = 0; k < 4; ++k) {
        float4 liw = *(const float4*)(a_ln_i_w + k * 128 + lane * 4);
        float4 lib = *(const float4*)(a_ln_i_b + k * 128 + lane * 4);
        float4 lhw = *(const float4*)(a_ln_h_w + k * 128 + lane * 4);
        float4 lhb = *(const float4*)(a_ln_h_b + k * 128 + lane * 4);
        const float* pw = &liw.x; const float* pb = &lib.x;
        const float* qw = &lhw.x; const float* qb = &lhb.x;
        #pragma unroll
        for (int q = 0; q < 4; ++q)
            g[k][q] = (ig[k][q] - muI) * rsI * pw[q] + pb[q]
                    + (hg[k][q] - muH) * rsH * qw[q] + qb[q];
    }

    float4 ac4 = *(const float4*)(total_c + (size_t)b * THW + 1024 + lane * 4);
    const float* acp = &ac4.x;
    float cpre[4];
    float sc = 0.f, sc2 = 0.f;
    #pragma unroll
    for (int q = 0; q < 4; ++q) {
        cpre[q] = sigf(g[1][q]) * acp[q] + sigf(g[0][q]) * tanhf(g[2][q]);
        sc += cpre[q]; sc2 += cpre[q] * cpre[q];
    }
    #pragma unroll
    for (int o = 16; o > 0; o >>= 1) {
        sc  += __shfl_xor_sync(0xffffffffu, sc, o);
        sc2 += __shfl_xor_sync(0xffffffffu, sc2, o);
    }
    const float mc = sc * (1.f / 128.f);
    const float rc = rsqrtf(sc2 * (1.f / 128.f) - mc * mc + LN_EPS);

    float4 lcw = *(const float4*)(a_ln_c_w + lane * 4);
    float4 lcb = *(const float4*)(a_ln_c_b + lane * 4);
    const float* cw = &lcw.x; const float* cb = &lcb.x;
    float acy[4], ada[4];
    #pragma unroll
    for (int q = 0; q < 4; ++q) {
        acy[q] = (cpre[q] - mc) * rc * cw[q] + cb[q];
        ada[q] = sigf(g[3][q]) * tanhf(acy[q]);
        sada[w][lane * 4 + q] = ada[q];
    }
    if (writeFull) {
        *(float4*)(out + OFF_H + (size_t)b * THW + 1024 + lane * 4) = make_float4(ada[0], ada[1], ada[2], ada[3]);
        *(float4*)(out + OFF_C + (size_t)b * THW + 1024 + lane * 4) = make_float4(acy[0], acy[1], acy[2], acy[3]);
    }
    __syncthreads();

    const int j = threadIdx.x & 255;
    const int rh = (threadIdx.x >> 8) * 8;
    float acc[8];
    #pragma unroll
    for (int r = 0; r < 8; ++r) acc[r] = 0.f;
    for (int a = 0; a < 128; ++a) {
        const float wv = __ldg(nwT + a * 256 + j);
        #pragma unroll
        for (int r = 0; r < 8; ++r) acc[r] += sada[rh + r][a] * wv;
    }
    const float zbias = (j < 128) ? norm_zw_b[j] : 0.f;
    const int b0 = blockIdx.x * 16 + rh;
    #pragma unroll
    for (int r = 0; r < 8; ++r) {
        float v = acc[r] + zbias;
        __nv_bfloat16 h = __float2bfloat16(v);
        zwzbHi[(size_t)(b0 + r) * 256 + j] = h;
        zwzbLo[(size_t)(b0 + r) * 256 + j] = __float2bfloat16(v - __bfloat162float(h));
    }
}

// ---------------- main pointwise (v3: fp16 gates input) ----------------
__device__ __forceinline__ void blockReduce4(float* v, int n, float* red, int t) {
    #pragma unroll
    for (int o = 16; o > 0; o >>= 1)
        for (int k = 0; k < 4; ++k) if (k < n) v[k] += __shfl_xor_sync(0xffffffffu, v[k], o);
    if ((t & 31) == 0)
        for (int k = 0; k < n; ++k) red[(t >> 5) * n + k] = v[k];
    __syncthreads();
    for (int k = 0; k < n; ++k) {
        float s = 0.f;
        for (int w = 0; w < 16; ++w) s += red[w * n + k];
        v[k] = s;
    }
    __syncthreads();
}

__global__ __launch_bounds__(512)
void main_pointwise(const __half* __restrict__ ing, const __half* __restrict__ hidg,
                    const float* __restrict__ total_c,
                    const float* __restrict__ ln_i_w, const float* __restrict__ ln_i_b,
                    const float* __restrict__ ln_h_w, const float* __restrict__ ln_h_b,
                    const float* __restrict__ ln_c_w, const float* __restrict__ ln_c_b,
                    float* __restrict__ out, int writeFull)
{
    __shared__ float sIn[4096];
    __shared__ float sHid[4096];
    __shared__ float red[64];
    const int b = blockIdx.x;
    const int t = threadIdx.x;

    // 4096 halves = 512 uint4 per row; one uint4 (8 halves) per thread
    const uint4* pi = (const uint4*)(ing  + (size_t)b * 4096);
    const uint4* ph = (const uint4*)(hidg + (size_t)b * 4096);
    float sums[4] = {0.f, 0.f, 0.f, 0.f};
    {
        uint4 v = pi[t];
        uint4 u = ph[t];
        const uint32_t* vw = &v.x;
        const uint32_t* uw = &u.x;
        #pragma unroll
        for (int k = 0; k < 4; ++k) {
            float2 f = __half22float2(*(const __half2*)&vw[k]);
            sIn[t * 8 + k * 2]     = f.x;
            sIn[t * 8 + k * 2 + 1] = f.y;
            sums[0] += f.x + f.y;
            sums[1] += f.x * f.x + f.y * f.y;
            float2 gH = __half22float2(*(const __half2*)&uw[k]);
            sHid[t * 8 + k * 2]     = gH.x;
            sHid[t * 8 + k * 2 + 1] = gH.y;
            sums[2] += gH.x + gH.y;
            sums[3] += gH.x * gH.x + gH.y * gH.y;
        }
    }
    __syncthreads();
    blockReduce4(sums, 4, red, t);
    const float muI = sums[0] * (1.f / 4096.f);
    const float rsI = rsqrtf(sums[1] * (1.f / 4096.f) - muI * muI + LN_EPS);
    const float muH = sums[2] * (1.f / 4096.f);
    const float rsH = rsqrtf(sums[3] * (1.f / 4096.f) - muH * muH + LN_EPS);

    for (int i = t; i < 1024; i += 512) {
        float4 vi = ((float4*)sIn)[i];
        float4 vh = ((float4*)sHid)[i];
        float4 liw = ((const float4*)ln_i_w)[i];
        float4 lib = ((const float4*)ln_i_b)[i];
        float4 lhw = ((const float4*)ln_h_w)[i];
        float4 lhb = ((const float4*)ln_h_b)[i];
        float4 g;
        g.x = (vi.x - muI) * rsI * liw.x + lib.x + (vh.x - muH) * rsH * lhw.x + lhb.x;
        g.y = (vi.y - muI) * rsI * liw.y + lib.y + (vh.y - muH) * rsH * lhw.y + lhb.y;
        g.z = (vi.z - muI) * rsI * liw.z + lib.z + (vh.z - muH) * rsH * lhw.z + lhb.z;
        g.w = (vi.w - muI) * rsI * liw.w + lib.w + (vh.w - muH) * rsH * lhw.w + lhb.w;
        ((float4*)sIn)[i] = g;
    }
    __syncthreads();

    float cp[2], gov[2];
    float csum[4] = {0.f, 0.f, 0.f, 0.f};
    #pragma unroll
    for (int k = 0; k < 2; ++k) {
        const int h = t + k * 512;
        float gi = sIn[h], gj = sIn[1024 + h], gf = sIn[2048 + h], go = sIn[3072 + h];
        float cx = total_c[(size_t)b * THW + h];
        float c = sigf(gf) * cx + sigf(gi) * tanhf(gj);
        cp[k] = c; gov[k] = go;
        csum[0] += c; csum[1] += c * c;
    }
    blockReduce4(csum, 2, red, t);
    const float mc = csum[0] * (1.f / 1024.f);
    const float rc = rsqrtf(csum[1] * (1.f / 1024.f) - mc * mc + LN_EPS);

    #pragma unroll
    for (int k = 0; k < 2; ++k) {
        const int h = t + k * 512;
        float cy = (cp[k] - mc) * rc * ln_c_w[h] + ln_c_b[h];
        float hy = sigf(gov[k]) * tanhf(cy);
        out[(size_t)b * 1024 + h] = hy;
        if (writeFull) {
            out[OFF_H + (size_t)b * THW + h] = hy;
            out[OFF_C + (size_t)b * THW + h] = cy;
        }
    }
}

// ---------------- launch ----------------
extern "C" void kernel_launch(void* const* d_in, const int* in_sizes, int n_in,
                              void* d_out, int out_size)
{
    const float* x           = (const float*)d_in[0];
    const float* total_h     = (const float*)d_in[1];
    const float* total_c     = (const float*)d_in[2];
    const float* w_ih        = (const float*)d_in[3];
    const float* w_hh        = (const float*)d_in[4];
    const float* b_ih        = (const float*)d_in[5];
    const float* b_hh        = (const float*)d_in[6];
    const float* ln_i_w      = (const float*)d_in[7];
    const float* ln_i_b      = (const float*)d_in[8];
    const float* ln_h_w      = (const float*)d_in[9];
    const float* ln_h_b      = (const float*)d_in[10];
    const float* ln_c_w      = (const float*)d_in[11];
    const float* ln_c_b      = (const float*)d_in[12];
    const float* norm_zw_w   = (const float*)d_in[13];
    const float* norm_zw_b   = (const float*)d_in[14];
    const float* norm_alpha_w= (const float*)d_in[15];
    const float* bias_zb_w   = (const float*)d_in[16];
    const float* bias_beta_w = (const float*)d_in[17];
    const float* a_w_ih      = (const float*)d_in[18];
    const float* a_w_hh      = (const float*)d_in[19];
    const float* a_ln_i_w    = (const float*)d_in[20];
    const float* a_ln_i_b    = (const float*)d_in[21];
    const float* a_ln_h_w    = (const float*)d_in[22];
    const float* a_ln_h_b    = (const float*)d_in[23];
    const float* a_ln_c_w    = (const float*)d_in[24];
    const float* a_ln_c_b    = (const float*)d_in[25];
    float* out = (float*)d_out;

    const int writeFull = (size_t)out_size >= OUT_FULL_SIZE ? 1 : 0;

    __half *xh_hi, *xh_lo, *wm_hi, *awih_hi, *ah_hi, *ah_lo, *awhh_hi, *gates;
    __nv_bfloat16 *zwzbHi, *zwzbLo, *aWHi, *aWLo, *bWHi, *bWLo;
    float *igpre, *hgpre, *nwT;
    cudaGetSymbolAddress((void**)&xh_hi, g_xh_hi);     cudaGetSymbolAddress((void**)&xh_lo, g_xh_lo);
    cudaGetSymbolAddress((void**)&wm_hi, g_wm_hi);
    cudaGetSymbolAddress((void**)&awih_hi, g_awih_hi);
    cudaGetSymbolAddress((void**)&ah_hi, g_ah_hi);     cudaGetSymbolAddress((void**)&ah_lo, g_ah_lo);
    cudaGetSymbolAddress((void**)&awhh_hi, g_awhh_hi);
    cudaGetSymbolAddress((void**)&zwzbHi, g_zwzbHi);   cudaGetSymbolAddress((void**)&zwzbLo, g_zwzbLo);
    cudaGetSymbolAddress((void**)&aWHi, g_aWHi);       cudaGetSymbolAddress((void**)&aWLo, g_aWLo);
    cudaGetSymbolAddress((void**)&bWHi, g_bWHi);       cudaGetSymbolAddress((void**)&bWLo, g_bWLo);
    cudaGetSymbolAddress((void**)&nwT, g_nwT);
    cudaGetSymbolAddress((void**)&igpre, g_igpre);     cudaGetSymbolAddress((void**)&hgpre, g_hgpre);
    cudaGetSymbolAddress((void**)&gates, g_gates);

    cudaFuncSetAttribute(gemm_main,    cudaFuncAttributeMaxDynamicSharedMemorySize, SMEM_MAIN);
    cudaFuncSetAttribute(gemm_adapter, cudaFuncAttributeMaxDynamicSharedMemorySize, SMEM_AD);

    // 0: all conversions
    split_all<<<9248, 256>>>(w_ih, w_hh, x, total_h, a_w_ih, a_w_hh,
                             norm_alpha_w, bias_beta_w, norm_zw_w, bias_zb_w,
                             wm_hi, xh_hi, xh_lo, ah_hi, ah_lo,
                             awih_hi, awhh_hi,
                             aWHi, aWLo, bWHi, bWLo, nwT);

    // 1: adapter GEMMs (dual, fp16x2)
    gemm_adapter<<<dim3(4, 32, 2), 512, SMEM_AD>>>(
        xh_hi, xh_lo, 2048, awih_hi, igpre, 512, 2048,
        ah_hi, ah_lo, 128, awhh_hi, hgpre, 512, 128);

    // 2: adapter pointwise + zwzb fused
    adapter_fused<<<Bsz / 16, 512>>>(
        igpre, hgpre, total_c,
        a_ln_i_w, a_ln_i_b, a_ln_h_w, a_ln_h_b, a_ln_c_w, a_ln_c_b,
        nwT, norm_zw_b, zwzbHi, zwzbLo, out, writeFull);

    // 3: main GEMMs (fp16x2, R15 2-stage) + fused epilogue, fp16 gates out
    gemm_main<<<dim3(16, 32, 2), 512, SMEM_MAIN>>>(
        xh_hi, xh_lo, 2048, 1024, wm_hi, (long)4096 * 1024,
        gates, 4096, (long)4096 * 4096, 1024,
        zwzbHi, zwzbLo, aWHi, aWLo, bWHi, bWLo, b_ih, b_hh);

    // 4: main pointwise (fp16 gates in)
    main_pointwise<<<Bsz, 512>>>(
        gates, gates + (size_t)4096 * 4096, total_c,
        ln_i_w, ln_i_b, ln_h_w, ln_h_b, ln_c_w, ln_c_b,
        out, writeFull);
}